// round 10
// baseline (speedup 1.0000x reference)
#include <cuda_runtime.h>
#include <cuda_bf16.h>
#include <cuda_fp8.h>
#include <cstdint>

// Problem constants
#define NN 50000
#define NE 800000
#define DI 256        // K for all layers
#define DO 128
#define BM 128
#define BN 128
#define IMG 10240            // 128 rows * 80B padded
#define STAGE (4 * IMG)      // Ah, Al, Bh, Bl

// ---------------- device scratch ----------------
__device__ __nv_bfloat16 g_xh[NN * DI];   // activation hi (bf16) — GEMM input
__device__ __nv_bfloat16 g_xl[NN * DI];   // activation lo (bf16) — GEMM input
__device__ __nv_bfloat16 g_hh[NN * DI];   // post-GEMM hi (bf16)
__device__ uint8_t       g_hl[NN * DI];   // post-GEMM lo (e4m3 of (h-hi)*256)
__device__ int   g_deg[NN];
__device__ float g_dinv[NN];
__device__ int   g_rowptr[NN + 1];
__device__ int   g_cursor[NN];
__device__ int   g_col[NE];
__device__ float g_norm[NE];
__device__ int   g_bsum[64];

// transposed bf16 weight images: Wt[n][k], k contiguous (256 wide)
__device__ __nv_bfloat16 g_W1h[DI * DI], g_W1l[DI * DI];
__device__ __nv_bfloat16 g_W2h[DI * DI], g_W2l[DI * DI];
__device__ __nv_bfloat16 g_W3h[DO * DI], g_W3l[DO * DI];

// ---------------- small helpers ----------------
__device__ __forceinline__ uint32_t smem_u32(const void* p) {
    uint32_t a;
    asm("{ .reg .u64 t; cvta.to.shared.u64 t, %1; cvt.u32.u64 %0, t; }" : "=r"(a) : "l"(p));
    return a;
}
__device__ __forceinline__ uint32_t pk2(float a, float b) {
    __nv_bfloat162 t = __floats2bfloat162_rn(a, b);
    return *reinterpret_cast<uint32_t*>(&t);
}
__device__ __forceinline__ float2 bf2f2(uint32_t u) {
    __nv_bfloat162 t = *reinterpret_cast<__nv_bfloat162*>(&u);
    return __bfloat1622float2(t);
}
__device__ __forceinline__ float2 fp8x2_f2(uint32_t u16) {
    __half2_raw hr = __nv_cvt_fp8x2_to_halfraw2((__nv_fp8x2_storage_t)u16, __NV_E4M3);
    return __half22float2(*reinterpret_cast<__half2*>(&hr));
}
__device__ __forceinline__ uint8_t f_fp8(float x) {
    return (uint8_t)__nv_cvt_float_to_fp8(x, __NV_SATFINITE, __NV_E4M3);
}
__device__ __forceinline__ void cpa16(uint32_t dst, const void* src, uint32_t sz) {
    asm volatile("cp.async.cg.shared.global [%0], [%1], 16, %2;"
                 :: "r"(dst), "l"(src), "r"(sz));
}
#define CP_COMMIT() asm volatile("cp.async.commit_group;" ::: "memory")
#define CP_WAIT1()  asm volatile("cp.async.wait_group 1;" ::: "memory")
#define CP_WAIT0()  asm volatile("cp.async.wait_group 0;" ::: "memory")

#define LDSM4(r, a) \
    asm volatile("ldmatrix.sync.aligned.m8n8.x4.shared.b16 {%0,%1,%2,%3}, [%4];" \
                 : "=r"((r)[0]), "=r"((r)[1]), "=r"((r)[2]), "=r"((r)[3]) : "r"(a))

#define MMA(ac, a, bb0, bb1) \
    asm volatile("mma.sync.aligned.m16n8k16.row.col.f32.bf16.bf16.f32 " \
                 "{%0,%1,%2,%3},{%4,%5,%6,%7},{%8,%9},{%0,%1,%2,%3};" \
                 : "+f"((ac)[0]), "+f"((ac)[1]), "+f"((ac)[2]), "+f"((ac)[3]) \
                 : "r"((a)[0]), "r"((a)[1]), "r"((a)[2]), "r"((a)[3]), \
                   "r"(bb0), "r"(bb1))

// ---------------- elementwise: x = qe * obj -> bf16 hi/lo (+ zero g_deg) ---
__global__ void k_had(const float4* __restrict__ a, const float4* __restrict__ b) {
    int i = blockIdx.x * blockDim.x + threadIdx.x;
    if (i < NN) g_deg[i] = 0;
    const int n4 = NN * DI / 4;
    if (i < n4) {
        float4 va = a[i], vb = b[i];
        float v0 = va.x * vb.x, v1 = va.y * vb.y, v2 = va.z * vb.z, v3 = va.w * vb.w;
        float h0 = __bfloat162float(__float2bfloat16_rn(v0));
        float h1 = __bfloat162float(__float2bfloat16_rn(v1));
        float h2 = __bfloat162float(__float2bfloat16_rn(v2));
        float h3 = __bfloat162float(__float2bfloat16_rn(v3));
        reinterpret_cast<uint2*>(g_xh)[i] = make_uint2(pk2(h0, h1), pk2(h2, h3));
        reinterpret_cast<uint2*>(g_xl)[i] =
            make_uint2(pk2(v0 - h0, v1 - h1), pk2(v2 - h2, v3 - h3));
    }
}

// ---------------- graph prep ----------------
__global__ void k_count(const int* __restrict__ ei) {
    int e = blockIdx.x * blockDim.x + threadIdx.x;
    if (e < NE) atomicAdd(&g_deg[ei[e]], 1);
}
__global__ __launch_bounds__(1024) void k_scan_block() {
    __shared__ int s[1024];
    int tid = threadIdx.x;
    int i = blockIdx.x * 1024 + tid;
    int v = (i < NN) ? g_deg[i] : 0;
    if (i < NN) g_dinv[i] = rsqrtf((float)(v + 1));
    s[tid] = v;
    __syncthreads();
    #pragma unroll
    for (int off = 1; off < 1024; off <<= 1) {
        int t = (tid >= off) ? s[tid - off] : 0;
        __syncthreads();
        s[tid] += t;
        __syncthreads();
    }
    if (i < NN) g_rowptr[i] = s[tid] - v;
    if (tid == 1023) g_bsum[blockIdx.x] = s[1023];
}
__global__ void k_scan_sums(int nblocks) {
    if (threadIdx.x == 0) {
        int acc = 0;
        for (int b = 0; b < nblocks; b++) { int v = g_bsum[b]; g_bsum[b] = acc; acc += v; }
    }
}
__global__ void k_scan_add() {
    int i = blockIdx.x * blockDim.x + threadIdx.x;
    if (i < NN) {
        int v = g_rowptr[i] + g_bsum[i >> 10];
        g_rowptr[i] = v;
        g_cursor[i] = v;
        if (i == 0) g_rowptr[NN] = NE;
    }
}
__global__ void k_fill(const int* __restrict__ ei) {
    int e = blockIdx.x * blockDim.x + threadIdx.x;
    if (e < NE) {
        int r = ei[e], c = ei[NE + e];
        int pos = atomicAdd(&g_cursor[r], 1);
        g_col[pos]  = c;
        g_norm[pos] = g_dinv[r] * g_dinv[c];
    }
}

// ---------------- weight pack (all 3 layers, one launch) ----------------
__global__ void k_pack_all(const float* __restrict__ W1,
                           const float* __restrict__ W2,
                           const float* __restrict__ W3) {
    const int T1 = DI * DI, T2 = 2 * DI * DI, T3 = 2 * DI * DI + DI * DO;
    for (int idx = blockIdx.x * blockDim.x + threadIdx.x; idx < T3;
         idx += gridDim.x * blockDim.x) {
        const float* W; __nv_bfloat16 *Wh, *Wl; int loc, N;
        if (idx < T1)      { W = W1; Wh = g_W1h; Wl = g_W1l; loc = idx;      N = DI; }
        else if (idx < T2) { W = W2; Wh = g_W2h; Wl = g_W2l; loc = idx - T1; N = DI; }
        else               { W = W3; Wh = g_W3h; Wl = g_W3l; loc = idx - T2; N = DO; }
        int k = loc / N, n = loc % N;
        float w = W[loc];
        __nv_bfloat16 hi = __float2bfloat16_rn(w);
        Wh[n * DI + k] = hi;
        Wl[n * DI + k] = __float2bfloat16_rn(w - __bfloat162float(hi));
    }
}

// ---------------- bf16-split tensor-core GEMM -> hi/lo compressed out -----
template <int N>
__global__ __launch_bounds__(256) void k_mma(int layer) {
    const __nv_bfloat16* Wh = (layer == 0) ? g_W1h : (layer == 1) ? g_W2h : g_W3h;
    const __nv_bfloat16* Wl = (layer == 0) ? g_W1l : (layer == 1) ? g_W2l : g_W3l;

    extern __shared__ char smem[];
    const uint32_t sb = smem_u32(smem);
    const int tid = threadIdx.x;
    const int lane = tid & 31, wid = tid >> 5;
    const int wm = (wid >> 1) * 32;
    const int wn = (wid & 1) * 64;
    const int rowBase = blockIdx.y * BM;
    const int n0 = blockIdx.x * BN;

    float acc[2][8][4];
    #pragma unroll
    for (int a = 0; a < 2; a++)
        #pragma unroll
        for (int b = 0; b < 8; b++)
            #pragma unroll
            for (int c = 0; c < 4; c++) acc[a][b][c] = 0.f;

    auto fill = [&](int s, int k0) {
        #pragma unroll
        for (int i = 0; i < 8; i++) {
            int c = tid + i * 256;
            int img = c >> 9;
            int r   = (c >> 2) & 127;
            int ch  = c & 3;
            uint32_t dst = sb + s * STAGE + img * IMG + r * 80 + ch * 16;
            const __nv_bfloat16* src;
            uint32_t sz = 16;
            if (img < 2) {
                int gr = rowBase + r;
                const __nv_bfloat16* p = (img == 0) ? g_xh : g_xl;
                if (gr >= NN) { gr = 0; sz = 0; }
                src = p + (size_t)gr * DI + k0 + ch * 8;
            } else {
                const __nv_bfloat16* p = (img == 2) ? Wh : Wl;
                src = p + (size_t)(n0 + r) * DI + k0 + ch * 8;
            }
            cpa16(dst, src, sz);
        }
    };

    fill(0, 0);
    CP_COMMIT();

    for (int step = 0; step < 8; step++) {
        const int s = step & 1;
        if (step < 7) { fill(s ^ 1, (step + 1) * 32); CP_COMMIT(); CP_WAIT1(); }
        else CP_WAIT0();
        __syncthreads();

        const uint32_t Ah = sb + s * STAGE;
        const uint32_t Al = Ah + IMG;
        const uint32_t Bh = Ah + 2 * IMG;
        const uint32_t Bl = Ah + 3 * IMG;

        #pragma unroll
        for (int ks = 0; ks < 2; ks++) {
            uint32_t ah[2][4], al[2][4], bh[4][4], bl[4][4];
            const int arow = (lane & 7) + ((lane >> 3) & 1) * 8;
            const int akb  = ks * 32 + (lane >> 4) * 16;
            #pragma unroll
            for (int mt = 0; mt < 2; mt++) {
                uint32_t off = (uint32_t)(wm + mt * 16 + arow) * 80 + akb;
                LDSM4(ah[mt], Ah + off);
                LDSM4(al[mt], Al + off);
            }
            const int brow = (lane & 7) + ((lane >> 4) & 1) * 8;
            const int bkb  = ks * 32 + ((lane >> 3) & 1) * 16;
            #pragma unroll
            for (int p = 0; p < 4; p++) {
                uint32_t off = (uint32_t)(wn + p * 16 + brow) * 80 + bkb;
                LDSM4(bh[p], Bh + off);
                LDSM4(bl[p], Bl + off);
            }
            #pragma unroll
            for (int mt = 0; mt < 2; mt++)
                #pragma unroll
                for (int p = 0; p < 4; p++) {
                    MMA(acc[mt][2 * p],     ah[mt], bh[p][0], bh[p][1]);
                    MMA(acc[mt][2 * p + 1], ah[mt], bh[p][2], bh[p][3]);
                    MMA(acc[mt][2 * p],     ah[mt], bl[p][0], bl[p][1]);
                    MMA(acc[mt][2 * p + 1], ah[mt], bl[p][2], bl[p][3]);
                    MMA(acc[mt][2 * p],     al[mt], bh[p][0], bh[p][1]);
                    MMA(acc[mt][2 * p + 1], al[mt], bh[p][2], bh[p][3]);
                }
        }
        __syncthreads();
    }

    // epilogue: write hi (bf16) + lo (e4m3 of residual*256)
    const int g = lane >> 2, t2 = (lane & 3) * 2;
    #pragma unroll
    for (int mt = 0; mt < 2; mt++) {
        #pragma unroll
        for (int half = 0; half < 2; half++) {
            int r = rowBase + wm + mt * 16 + g + half * 8;
            if (r >= NN) continue;
            #pragma unroll
            for (int nt = 0; nt < 8; nt++) {
                int col = n0 + wn + nt * 8 + t2;
                float f0 = acc[mt][nt][2 * half + 0];
                float f1 = acc[mt][nt][2 * half + 1];
                __nv_bfloat16 h0 = __float2bfloat16_rn(f0);
                __nv_bfloat16 h1 = __float2bfloat16_rn(f1);
                float h0f = __bfloat162float(h0), h1f = __bfloat162float(h1);
                *reinterpret_cast<uint32_t*>(&g_hh[(size_t)r * N + col]) =
                    pk2(h0f, h1f);
                uchar2 lv;
                lv.x = f_fp8((f0 - h0f) * 256.f);
                lv.y = f_fp8((f1 - h1f) * 256.f);
                *reinterpret_cast<uchar2*>(&g_hl[(size_t)r * N + col]) = lv;
            }
        }
    }
}

// ---------------- aggregation over compressed hi/lo features ----------------
template <int D, bool HIDDEN>
__global__ void k_agg(const float* __restrict__ bias, float* __restrict__ outp) {
    const int i = blockIdx.x;
    const int t = threadIdx.x;            // 0 .. D/4-1
    const int beg = g_rowptr[i];
    const int end = g_rowptr[i + 1];
    const float di = g_dinv[i];
    const uint2* __restrict__ hh = reinterpret_cast<const uint2*>(g_hh);
    const uint32_t* __restrict__ hl = reinterpret_cast<const uint32_t*>(g_hl);

    float4 ah = make_float4(0.f, 0.f, 0.f, 0.f);   // sum w*hi
    float4 al = make_float4(0.f, 0.f, 0.f, 0.f);   // sum w*lo (scaled 256)

    // self term
    {
        const float w = di * di;
        size_t o = (size_t)i * (D / 4) + t;
        uint2 hv = hh[o]; uint32_t lv = hl[o];
        float2 a01 = bf2f2(hv.x), a23 = bf2f2(hv.y);
        float2 l01 = fp8x2_f2(lv & 0xFFFFu), l23 = fp8x2_f2(lv >> 16);
        ah.x += w * a01.x; ah.y += w * a01.y; ah.z += w * a23.x; ah.w += w * a23.y;
        al.x += w * l01.x; al.y += w * l01.y; al.z += w * l23.x; al.w += w * l23.y;
    }
    for (int e = beg; e < end; e++) {
        int c = g_col[e];
        float w = g_norm[e];
        size_t o = (size_t)c * (D / 4) + t;
        uint2 hv = hh[o]; uint32_t lv = hl[o];
        float2 a01 = bf2f2(hv.x), a23 = bf2f2(hv.y);
        float2 l01 = fp8x2_f2(lv & 0xFFFFu), l23 = fp8x2_f2(lv >> 16);
        ah.x += w * a01.x; ah.y += w * a01.y; ah.z += w * a23.x; ah.w += w * a23.y;
        al.x += w * l01.x; al.y += w * l01.y; al.z += w * l23.x; al.w += w * l23.y;
    }

    float4 bv = reinterpret_cast<const float4*>(bias)[t];
    const float s = 1.f / 256.f;
    float4 acc;
    acc.x = ah.x + al.x * s + bv.x;
    acc.y = ah.y + al.y * s + bv.y;
    acc.z = ah.z + al.z * s + bv.z;
    acc.w = ah.w + al.w * s + bv.w;

    if (HIDDEN) {
        acc.x = fmaxf(acc.x, 0.f); acc.y = fmaxf(acc.y, 0.f);
        acc.z = fmaxf(acc.z, 0.f); acc.w = fmaxf(acc.w, 0.f);
        float h0 = __bfloat162float(__float2bfloat16_rn(acc.x));
        float h1 = __bfloat162float(__float2bfloat16_rn(acc.y));
        float h2 = __bfloat162float(__float2bfloat16_rn(acc.z));
        float h3 = __bfloat162float(__float2bfloat16_rn(acc.w));
        size_t o = (size_t)i * (D / 4) + t;
        reinterpret_cast<uint2*>(g_xh)[o] = make_uint2(pk2(h0, h1), pk2(h2, h3));
        reinterpret_cast<uint2*>(g_xl)[o] =
            make_uint2(pk2(acc.x - h0, acc.y - h1), pk2(acc.z - h2, acc.w - h3));
    } else {
        reinterpret_cast<float4*>(outp)[(size_t)i * (D / 4) + t] = acc;
    }
}

// ---------------- launch ----------------
extern "C" void kernel_launch(void* const* d_in, const int* in_sizes, int n_in,
                              void* d_out, int out_size) {
    const float* qe  = (const float*)d_in[0];
    const float* obj = (const float*)d_in[1];
    const int*   ei  = (const int*)d_in[2];
    const float* W1 = (const float*)d_in[3];
    const float* b1 = (const float*)d_in[4];
    const float* W2 = (const float*)d_in[5];
    const float* b2 = (const float*)d_in[6];
    const float* W3 = (const float*)d_in[7];
    const float* b3 = (const float*)d_in[8];
    float* out = (float*)d_out;

    const int SMEM = 2 * STAGE;   // 81920
    static bool attr_done = false;
    if (!attr_done) {
        cudaFuncSetAttribute(k_mma<256>, cudaFuncAttributeMaxDynamicSharedMemorySize, SMEM);
        cudaFuncSetAttribute(k_mma<128>, cudaFuncAttributeMaxDynamicSharedMemorySize, SMEM);
        attr_done = true;
    }

    // x = qe * obj (bf16 hi/lo) + zero deg
    k_had<<<(NN * DI / 4 + 255) / 256, 256>>>((const float4*)qe, (const float4*)obj);
    // weight pack (one launch, all layers)
    k_pack_all<<<296, 256>>>(W1, W2, W3);

    // graph prep
    k_count<<<(NE + 255) / 256, 256>>>(ei);
    const int nsb = (NN + 1023) / 1024;
    k_scan_block<<<nsb, 1024>>>();
    k_scan_sums<<<1, 32>>>(nsb);
    k_scan_add<<<(NN + 255) / 256, 256>>>();
    k_fill<<<(NE + 255) / 256, 256>>>(ei);

    const int mb = (NN + BM - 1) / BM;    // 391

    // layer 1
    k_mma<256><<<dim3(2, mb), 256, SMEM>>>(0);
    k_agg<DI, true><<<NN, DI / 4>>>(b1, nullptr);
    // layer 2
    k_mma<256><<<dim3(2, mb), 256, SMEM>>>(1);
    k_agg<DI, true><<<NN, DI / 4>>>(b2, nullptr);
    // layer 3
    k_mma<128><<<dim3(1, mb), 256, SMEM>>>(2);
    k_agg<DO, false><<<NN, DO / 4>>>(b3, out);
}

// round 11
// speedup vs baseline: 1.1577x; 1.1577x over previous
#include <cuda_runtime.h>
#include <cuda_bf16.h>
#include <cstdint>

// Problem constants
#define NN 50000
#define NE 800000
#define DI 256        // K for all layers
#define DO 128
#define BM 128
#define BN 128
#define IMG 10240            // 128 rows * 80B padded
#define STAGE (4 * IMG)      // layer-3 kernel: Ah, Al, Bh, Bl
#define STAGE2 61440         // wide kernel: Ah,Al (2*10240) + Bh,Bl (2*20480)

// ---------------- device scratch ----------------
__device__ __nv_bfloat16 g_xh[NN * DI];   // activation hi (bf16)
__device__ __nv_bfloat16 g_xl[NN * DI];   // activation lo (bf16)
__device__ float g_h[NN * DI];            // post-GEMM fp32
__device__ int   g_deg[NN];
__device__ float g_dinv[NN];
__device__ int   g_rowptr[NN + 1];
__device__ int   g_cursor[NN];
__device__ int   g_col[NE];
__device__ float g_norm[NE];
__device__ int   g_bsum[64];

// transposed bf16 weight images: Wt[n][k], k contiguous (256 wide)
__device__ __nv_bfloat16 g_W1h[DI * DI], g_W1l[DI * DI];
__device__ __nv_bfloat16 g_W2h[DI * DI], g_W2l[DI * DI];
__device__ __nv_bfloat16 g_W3h[DO * DI], g_W3l[DO * DI];

// ---------------- small helpers ----------------
__device__ __forceinline__ uint32_t smem_u32(const void* p) {
    uint32_t a;
    asm("{ .reg .u64 t; cvta.to.shared.u64 t, %1; cvt.u32.u64 %0, t; }" : "=r"(a) : "l"(p));
    return a;
}
__device__ __forceinline__ uint32_t pk2(float a, float b) {
    __nv_bfloat162 t = __floats2bfloat162_rn(a, b);
    return *reinterpret_cast<uint32_t*>(&t);
}
__device__ __forceinline__ void cpa16(uint32_t dst, const void* src, uint32_t sz) {
    asm volatile("cp.async.cg.shared.global [%0], [%1], 16, %2;"
                 :: "r"(dst), "l"(src), "r"(sz));
}
#define CP_COMMIT() asm volatile("cp.async.commit_group;" ::: "memory")
#define CP_WAIT1()  asm volatile("cp.async.wait_group 1;" ::: "memory")
#define CP_WAIT0()  asm volatile("cp.async.wait_group 0;" ::: "memory")

#define LDSM4(r, a) \
    asm volatile("ldmatrix.sync.aligned.m8n8.x4.shared.b16 {%0,%1,%2,%3}, [%4];" \
                 : "=r"((r)[0]), "=r"((r)[1]), "=r"((r)[2]), "=r"((r)[3]) : "r"(a))

#define MMA(ac, a, bb0, bb1) \
    asm volatile("mma.sync.aligned.m16n8k16.row.col.f32.bf16.bf16.f32 " \
                 "{%0,%1,%2,%3},{%4,%5,%6,%7},{%8,%9},{%0,%1,%2,%3};" \
                 : "+f"((ac)[0]), "+f"((ac)[1]), "+f"((ac)[2]), "+f"((ac)[3]) \
                 : "r"((a)[0]), "r"((a)[1]), "r"((a)[2]), "r"((a)[3]), \
                   "r"(bb0), "r"(bb1))

// ---------------- elementwise: x = qe * obj -> bf16 hi/lo (+ zero g_deg) ---
__global__ void k_had(const float4* __restrict__ a, const float4* __restrict__ b) {
    int i = blockIdx.x * blockDim.x + threadIdx.x;
    if (i < NN) g_deg[i] = 0;
    const int n4 = NN * DI / 4;
    if (i < n4) {
        float4 va = a[i], vb = b[i];
        float v0 = va.x * vb.x, v1 = va.y * vb.y, v2 = va.z * vb.z, v3 = va.w * vb.w;
        float h0 = __bfloat162float(__float2bfloat16_rn(v0));
        float h1 = __bfloat162float(__float2bfloat16_rn(v1));
        float h2 = __bfloat162float(__float2bfloat16_rn(v2));
        float h3 = __bfloat162float(__float2bfloat16_rn(v3));
        reinterpret_cast<uint2*>(g_xh)[i] = make_uint2(pk2(h0, h1), pk2(h2, h3));
        reinterpret_cast<uint2*>(g_xl)[i] =
            make_uint2(pk2(v0 - h0, v1 - h1), pk2(v2 - h2, v3 - h3));
    }
}

// ---------------- graph prep ----------------
__global__ void k_count(const int* __restrict__ ei) {
    int e = blockIdx.x * blockDim.x + threadIdx.x;
    if (e < NE) atomicAdd(&g_deg[ei[e]], 1);
}
__global__ __launch_bounds__(1024) void k_scan_block() {
    __shared__ int s[1024];
    int tid = threadIdx.x;
    int i = blockIdx.x * 1024 + tid;
    int v = (i < NN) ? g_deg[i] : 0;
    if (i < NN) g_dinv[i] = rsqrtf((float)(v + 1));
    s[tid] = v;
    __syncthreads();
    #pragma unroll
    for (int off = 1; off < 1024; off <<= 1) {
        int t = (tid >= off) ? s[tid - off] : 0;
        __syncthreads();
        s[tid] += t;
        __syncthreads();
    }
    if (i < NN) g_rowptr[i] = s[tid] - v;
    if (tid == 1023) g_bsum[blockIdx.x] = s[1023];
}
__global__ void k_scan_sums(int nblocks) {
    if (threadIdx.x == 0) {
        int acc = 0;
        for (int b = 0; b < nblocks; b++) { int v = g_bsum[b]; g_bsum[b] = acc; acc += v; }
    }
}
__global__ void k_scan_add() {
    int i = blockIdx.x * blockDim.x + threadIdx.x;
    if (i < NN) {
        int v = g_rowptr[i] + g_bsum[i >> 10];
        g_rowptr[i] = v;
        g_cursor[i] = v;
        if (i == 0) g_rowptr[NN] = NE;
    }
}
__global__ void k_fill(const int* __restrict__ ei) {
    int e = blockIdx.x * blockDim.x + threadIdx.x;
    if (e < NE) {
        int r = ei[e], c = ei[NE + e];
        int pos = atomicAdd(&g_cursor[r], 1);
        g_col[pos]  = c;
        g_norm[pos] = g_dinv[r] * g_dinv[c];
    }
}

// ---------------- weight pack (all 3 layers, one launch) ----------------
__global__ void k_pack_all(const float* __restrict__ W1,
                           const float* __restrict__ W2,
                           const float* __restrict__ W3) {
    const int T1 = DI * DI, T2 = 2 * DI * DI, T3 = 2 * DI * DI + DI * DO;
    for (int idx = blockIdx.x * blockDim.x + threadIdx.x; idx < T3;
         idx += gridDim.x * blockDim.x) {
        const float* W; __nv_bfloat16 *Wh, *Wl; int loc, N;
        if (idx < T1)      { W = W1; Wh = g_W1h; Wl = g_W1l; loc = idx;      N = DI; }
        else if (idx < T2) { W = W2; Wh = g_W2h; Wl = g_W2l; loc = idx - T1; N = DI; }
        else               { W = W3; Wh = g_W3h; Wl = g_W3l; loc = idx - T2; N = DO; }
        int k = loc / N, n = loc % N;
        float w = W[loc];
        __nv_bfloat16 hi = __float2bfloat16_rn(w);
        Wh[n * DI + k] = hi;
        Wl[n * DI + k] = __float2bfloat16_rn(w - __bfloat162float(hi));
    }
}

// ---------------- wide GEMM (layers 1-2): BM=128, BN=256, 512 threads ------
// g_h[M,256] = (xh+xl)[M,256] @ (Wh+Wl)^T, 3-term bf16 split, fp32 accum.
__global__ __launch_bounds__(512) void k_mma_wide(int layer) {
    const __nv_bfloat16* Wh = (layer == 0) ? g_W1h : g_W2h;
    const __nv_bfloat16* Wl = (layer == 0) ? g_W1l : g_W2l;

    extern __shared__ char smem[];
    const uint32_t sb = smem_u32(smem);
    const int tid = threadIdx.x;
    const int lane = tid & 31, wid = tid >> 5;     // 16 warps
    const int wm = (wid >> 2) * 32;                 // 0,32,64,96
    const int wn = (wid & 3) * 64;                  // 0,64,128,192
    const int rowBase = blockIdx.y * BM;

    float acc[2][8][4];
    #pragma unroll
    for (int a = 0; a < 2; a++)
        #pragma unroll
        for (int b = 0; b < 8; b++)
            #pragma unroll
            for (int c = 0; c < 4; c++) acc[a][b][c] = 0.f;

    // 3072 16B chunks per stage: A 2x(128x4), B 2x(256x4)
    auto fill = [&](int s, int k0) {
        #pragma unroll
        for (int i = 0; i < 6; i++) {
            int c = tid + i * 512;
            uint32_t dst;
            const __nv_bfloat16* src;
            uint32_t sz = 16;
            if (c < 1024) {                       // A images
                int img = c >> 9, r = (c >> 2) & 127, ch = c & 3;
                dst = sb + s * STAGE2 + img * 10240 + r * 80 + ch * 16;
                int gr = rowBase + r;
                const __nv_bfloat16* p = (img == 0) ? g_xh : g_xl;
                if (gr >= NN) { gr = 0; sz = 0; }
                src = p + (size_t)gr * DI + k0 + ch * 8;
            } else {                              // B images
                int d = c - 1024;
                int img = d >> 10, r = (d >> 2) & 255, ch = d & 3;
                dst = sb + s * STAGE2 + 20480 + img * 20480 + r * 80 + ch * 16;
                const __nv_bfloat16* p = (img == 0) ? Wh : Wl;
                src = p + (size_t)r * DI + k0 + ch * 8;
            }
            cpa16(dst, src, sz);
        }
    };

    fill(0, 0);
    CP_COMMIT();

    for (int step = 0; step < 8; step++) {
        const int s = step & 1;
        if (step < 7) { fill(s ^ 1, (step + 1) * 32); CP_COMMIT(); CP_WAIT1(); }
        else CP_WAIT0();
        __syncthreads();

        const uint32_t Ah = sb + s * STAGE2;
        const uint32_t Al = Ah + 10240;
        const uint32_t Bh = Ah + 20480;
        const uint32_t Bl = Ah + 40960;

        #pragma unroll
        for (int ks = 0; ks < 2; ks++) {
            uint32_t ah[2][4], al[2][4];
            const int arow = (lane & 7) + ((lane >> 3) & 1) * 8;
            const int akb  = ks * 32 + (lane >> 4) * 16;
            #pragma unroll
            for (int mt = 0; mt < 2; mt++) {
                uint32_t off = (uint32_t)(wm + mt * 16 + arow) * 80 + akb;
                LDSM4(ah[mt], Ah + off);
                LDSM4(al[mt], Al + off);
            }
            const int brow = (lane & 7) + ((lane >> 4) & 1) * 8;
            const int bkb  = ks * 32 + ((lane >> 3) & 1) * 16;
            #pragma unroll
            for (int p = 0; p < 4; p++) {
                uint32_t bh[4], bl[4];
                uint32_t off = (uint32_t)(wn + p * 16 + brow) * 80 + bkb;
                LDSM4(bh, Bh + off);
                LDSM4(bl, Bl + off);
                #pragma unroll
                for (int mt = 0; mt < 2; mt++) {
                    MMA(acc[mt][2 * p],     ah[mt], bh[0], bh[1]);
                    MMA(acc[mt][2 * p + 1], ah[mt], bh[2], bh[3]);
                    MMA(acc[mt][2 * p],     ah[mt], bl[0], bl[1]);
                    MMA(acc[mt][2 * p + 1], ah[mt], bl[2], bl[3]);
                    MMA(acc[mt][2 * p],     al[mt], bh[0], bh[1]);
                    MMA(acc[mt][2 * p + 1], al[mt], bh[2], bh[3]);
                }
            }
        }
        __syncthreads();
    }

    const int g = lane >> 2, t2 = (lane & 3) * 2;
    #pragma unroll
    for (int mt = 0; mt < 2; mt++) {
        int r0 = rowBase + wm + mt * 16 + g;
        #pragma unroll
        for (int nt = 0; nt < 8; nt++) {
            int col = wn + nt * 8 + t2;
            if (r0 < NN)
                *reinterpret_cast<float2*>(&g_h[(size_t)r0 * 256 + col]) =
                    make_float2(acc[mt][nt][0], acc[mt][nt][1]);
            if (r0 + 8 < NN)
                *reinterpret_cast<float2*>(&g_h[(size_t)(r0 + 8) * 256 + col]) =
                    make_float2(acc[mt][nt][2], acc[mt][nt][3]);
        }
    }
}

// ---------------- layer-3 GEMM: N=128, 256 threads (proven) ----------------
__global__ __launch_bounds__(256) void k_mma3() {
    const __nv_bfloat16* Wh = g_W3h;
    const __nv_bfloat16* Wl = g_W3l;
    const int N = 128;

    extern __shared__ char smem[];
    const uint32_t sb = smem_u32(smem);
    const int tid = threadIdx.x;
    const int lane = tid & 31, wid = tid >> 5;
    const int wm = (wid >> 1) * 32;
    const int wn = (wid & 1) * 64;
    const int rowBase = blockIdx.y * BM;

    float acc[2][8][4];
    #pragma unroll
    for (int a = 0; a < 2; a++)
        #pragma unroll
        for (int b = 0; b < 8; b++)
            #pragma unroll
            for (int c = 0; c < 4; c++) acc[a][b][c] = 0.f;

    auto fill = [&](int s, int k0) {
        #pragma unroll
        for (int i = 0; i < 8; i++) {
            int c = tid + i * 256;
            int img = c >> 9;
            int r   = (c >> 2) & 127;
            int ch  = c & 3;
            uint32_t dst = sb + s * STAGE + img * IMG + r * 80 + ch * 16;
            const __nv_bfloat16* src;
            uint32_t sz = 16;
            if (img < 2) {
                int gr = rowBase + r;
                const __nv_bfloat16* p = (img == 0) ? g_xh : g_xl;
                if (gr >= NN) { gr = 0; sz = 0; }
                src = p + (size_t)gr * DI + k0 + ch * 8;
            } else {
                const __nv_bfloat16* p = (img == 2) ? Wh : Wl;
                src = p + (size_t)r * DI + k0 + ch * 8;
            }
            cpa16(dst, src, sz);
        }
    };

    fill(0, 0);
    CP_COMMIT();

    for (int step = 0; step < 8; step++) {
        const int s = step & 1;
        if (step < 7) { fill(s ^ 1, (step + 1) * 32); CP_COMMIT(); CP_WAIT1(); }
        else CP_WAIT0();
        __syncthreads();

        const uint32_t Ah = sb + s * STAGE;
        const uint32_t Al = Ah + IMG;
        const uint32_t Bh = Ah + 2 * IMG;
        const uint32_t Bl = Ah + 3 * IMG;

        #pragma unroll
        for (int ks = 0; ks < 2; ks++) {
            uint32_t ah[2][4], al[2][4];
            const int arow = (lane & 7) + ((lane >> 3) & 1) * 8;
            const int akb  = ks * 32 + (lane >> 4) * 16;
            #pragma unroll
            for (int mt = 0; mt < 2; mt++) {
                uint32_t off = (uint32_t)(wm + mt * 16 + arow) * 80 + akb;
                LDSM4(ah[mt], Ah + off);
                LDSM4(al[mt], Al + off);
            }
            const int brow = (lane & 7) + ((lane >> 4) & 1) * 8;
            const int bkb  = ks * 32 + ((lane >> 3) & 1) * 16;
            #pragma unroll
            for (int p = 0; p < 4; p++) {
                uint32_t bh[4], bl[4];
                uint32_t off = (uint32_t)(wn + p * 16 + brow) * 80 + bkb;
                LDSM4(bh, Bh + off);
                LDSM4(bl, Bl + off);
                #pragma unroll
                for (int mt = 0; mt < 2; mt++) {
                    MMA(acc[mt][2 * p],     ah[mt], bh[0], bh[1]);
                    MMA(acc[mt][2 * p + 1], ah[mt], bh[2], bh[3]);
                    MMA(acc[mt][2 * p],     ah[mt], bl[0], bl[1]);
                    MMA(acc[mt][2 * p + 1], ah[mt], bl[2], bl[3]);
                    MMA(acc[mt][2 * p],     al[mt], bh[0], bh[1]);
                    MMA(acc[mt][2 * p + 1], al[mt], bh[2], bh[3]);
                }
            }
        }
        __syncthreads();
    }

    const int g = lane >> 2, t2 = (lane & 3) * 2;
    #pragma unroll
    for (int mt = 0; mt < 2; mt++) {
        int r0 = rowBase + wm + mt * 16 + g;
        #pragma unroll
        for (int nt = 0; nt < 8; nt++) {
            int col = wn + nt * 8 + t2;
            if (r0 < NN)
                *reinterpret_cast<float2*>(&g_h[(size_t)r0 * N + col]) =
                    make_float2(acc[mt][nt][0], acc[mt][nt][1]);
            if (r0 + 8 < NN)
                *reinterpret_cast<float2*>(&g_h[(size_t)(r0 + 8) * N + col]) =
                    make_float2(acc[mt][nt][2], acc[mt][nt][3]);
        }
    }
}

// ---------------- aggregation (round-5 proven form) ----------------
template <int D, bool HIDDEN>
__global__ void k_agg(const float* __restrict__ bias, float* __restrict__ outp) {
    const int i = blockIdx.x;
    const int t = threadIdx.x;
    const int beg = g_rowptr[i];
    const int end = g_rowptr[i + 1];
    const float di = g_dinv[i];
    const float4* __restrict__ h4 = reinterpret_cast<const float4*>(g_h);

    float4 acc = h4[(size_t)i * (D / 4) + t];
    const float s = di * di;
    acc.x *= s; acc.y *= s; acc.z *= s; acc.w *= s;

    for (int e = beg; e < end; e++) {
        int c = g_col[e];
        float w = g_norm[e];
        float4 v = h4[(size_t)c * (D / 4) + t];
        acc.x += w * v.x; acc.y += w * v.y; acc.z += w * v.z; acc.w += w * v.w;
    }

    float4 bv = reinterpret_cast<const float4*>(bias)[t];
    acc.x += bv.x; acc.y += bv.y; acc.z += bv.z; acc.w += bv.w;

    if (HIDDEN) {
        acc.x = fmaxf(acc.x, 0.f); acc.y = fmaxf(acc.y, 0.f);
        acc.z = fmaxf(acc.z, 0.f); acc.w = fmaxf(acc.w, 0.f);
        float h0 = __bfloat162float(__float2bfloat16_rn(acc.x));
        float h1 = __bfloat162float(__float2bfloat16_rn(acc.y));
        float h2 = __bfloat162float(__float2bfloat16_rn(acc.z));
        float h3 = __bfloat162float(__float2bfloat16_rn(acc.w));
        size_t o = (size_t)i * (D / 4) + t;
        reinterpret_cast<uint2*>(g_xh)[o] = make_uint2(pk2(h0, h1), pk2(h2, h3));
        reinterpret_cast<uint2*>(g_xl)[o] =
            make_uint2(pk2(acc.x - h0, acc.y - h1), pk2(acc.z - h2, acc.w - h3));
    } else {
        reinterpret_cast<float4*>(outp)[(size_t)i * (D / 4) + t] = acc;
    }
}

// ---------------- launch ----------------
extern "C" void kernel_launch(void* const* d_in, const int* in_sizes, int n_in,
                              void* d_out, int out_size) {
    const float* qe  = (const float*)d_in[0];
    const float* obj = (const float*)d_in[1];
    const int*   ei  = (const int*)d_in[2];
    const float* W1 = (const float*)d_in[3];
    const float* b1 = (const float*)d_in[4];
    const float* W2 = (const float*)d_in[5];
    const float* b2 = (const float*)d_in[6];
    const float* W3 = (const float*)d_in[7];
    const float* b3 = (const float*)d_in[8];
    float* out = (float*)d_out;

    const int SMEM_W = 2 * STAGE2;   // 122880
    const int SMEM_3 = 2 * STAGE;    // 81920
    static bool attr_done = false;
    if (!attr_done) {
        cudaFuncSetAttribute(k_mma_wide, cudaFuncAttributeMaxDynamicSharedMemorySize, SMEM_W);
        cudaFuncSetAttribute(k_mma3, cudaFuncAttributeMaxDynamicSharedMemorySize, SMEM_3);
        attr_done = true;
    }

    // x = qe * obj (bf16 hi/lo) + zero deg
    k_had<<<(NN * DI / 4 + 255) / 256, 256>>>((const float4*)qe, (const float4*)obj);
    // weight pack (one launch, all layers)
    k_pack_all<<<296, 256>>>(W1, W2, W3);

    // graph prep
    k_count<<<(NE + 255) / 256, 256>>>(ei);
    const int nsb = (NN + 1023) / 1024;
    k_scan_block<<<nsb, 1024>>>();
    k_scan_sums<<<1, 32>>>(nsb);
    k_scan_add<<<(NN + 255) / 256, 256>>>();
    k_fill<<<(NE + 255) / 256, 256>>>(ei);

    const int mb = (NN + BM - 1) / BM;    // 391

    // layer 1
    k_mma_wide<<<dim3(1, mb), 512, SMEM_W>>>(0);
    k_agg<DI, true><<<NN, DI / 4>>>(b1, nullptr);
    // layer 2
    k_mma_wide<<<dim3(1, mb), 512, SMEM_W>>>(1);
    k_agg<DI, true><<<NN, DI / 4>>>(b2, nullptr);
    // layer 3
    k_mma3<<<dim3(1, mb), 256, SMEM_3>>>();
    k_agg<DO, false><<<NN, DO / 4>>>(b3, out);
}

// round 13
// speedup vs baseline: 1.1808x; 1.0200x over previous
#include <cuda_runtime.h>
#include <cuda_bf16.h>
#include <cstdint>

// Problem constants
#define NN 50000
#define NE 800000
#define DI 256        // K for all layers
#define DO 128
#define BM 128
#define IMG 10240            // 128 rows * 80B padded
#define STAGE (4 * IMG)      // layer-3 kernel: Ah, Al, Bh, Bl
#define STAGE2 61440         // wide kernel: Ah,Al (2*10240) + Bh,Bl (2*20480)
#define NSB 49               // scan blocks: ceil(50000/1024)

// ---------------- device scratch ----------------
__device__ __nv_bfloat16 g_xh[NN * DI];   // activation hi (bf16)
__device__ __nv_bfloat16 g_xl[NN * DI];   // activation lo (bf16)
__device__ float g_h[NN * DI];            // post-GEMM fp32
__device__ int   g_deg[NN];
__device__ float g_dinv[NN];
__device__ int   g_rowptr[NN + 1];
__device__ int   g_cursor[NN];
__device__ int   g_col[NE];
__device__ float g_norm[NE];
__device__ int   g_bsum[64];

// transposed bf16 weight images: Wt[n][k], k contiguous (256 wide)
__device__ __nv_bfloat16 g_W1h[DI * DI], g_W1l[DI * DI];
__device__ __nv_bfloat16 g_W2h[DI * DI], g_W2l[DI * DI];
__device__ __nv_bfloat16 g_W3h[DO * DI], g_W3l[DO * DI];

// ---------------- small helpers ----------------
__device__ __forceinline__ uint32_t smem_u32(const void* p) {
    uint32_t a;
    asm("{ .reg .u64 t; cvta.to.shared.u64 t, %1; cvt.u32.u64 %0, t; }" : "=r"(a) : "l"(p));
    return a;
}
__device__ __forceinline__ uint32_t pk2(float a, float b) {
    __nv_bfloat162 t = __floats2bfloat162_rn(a, b);
    return *reinterpret_cast<uint32_t*>(&t);
}
__device__ __forceinline__ void cpa16(uint32_t dst, const void* src, uint32_t sz) {
    asm volatile("cp.async.cg.shared.global [%0], [%1], 16, %2;"
                 :: "r"(dst), "l"(src), "r"(sz));
}
#define CP_COMMIT() asm volatile("cp.async.commit_group;" ::: "memory")
#define CP_WAIT1()  asm volatile("cp.async.wait_group 1;" ::: "memory")
#define CP_WAIT0()  asm volatile("cp.async.wait_group 0;" ::: "memory")

#define LDSM4(r, a) \
    asm volatile("ldmatrix.sync.aligned.m8n8.x4.shared.b16 {%0,%1,%2,%3}, [%4];" \
                 : "=r"((r)[0]), "=r"((r)[1]), "=r"((r)[2]), "=r"((r)[3]) : "r"(a))

#define MMA(ac, a, bb0, bb1) \
    asm volatile("mma.sync.aligned.m16n8k16.row.col.f32.bf16.bf16.f32 " \
                 "{%0,%1,%2,%3},{%4,%5,%6,%7},{%8,%9},{%0,%1,%2,%3};" \
                 : "+f"((ac)[0]), "+f"((ac)[1]), "+f"((ac)[2]), "+f"((ac)[3]) \
                 : "r"((a)[0]), "r"((a)[1]), "r"((a)[2]), "r"((a)[3]), \
                   "r"(bb0), "r"(bb1))

// ---------------- launch 1: x = qe * obj -> bf16 hi/lo (+ zero g_deg) -----
__global__ void k_had(const float4* __restrict__ a, const float4* __restrict__ b) {
    int i = blockIdx.x * blockDim.x + threadIdx.x;
    if (i < NN) g_deg[i] = 0;
    const int n4 = NN * DI / 4;
    if (i < n4) {
        float4 va = a[i], vb = b[i];
        float v0 = va.x * vb.x, v1 = va.y * vb.y, v2 = va.z * vb.z, v3 = va.w * vb.w;
        float h0 = __bfloat162float(__float2bfloat16_rn(v0));
        float h1 = __bfloat162float(__float2bfloat16_rn(v1));
        float h2 = __bfloat162float(__float2bfloat16_rn(v2));
        float h3 = __bfloat162float(__float2bfloat16_rn(v3));
        reinterpret_cast<uint2*>(g_xh)[i] = make_uint2(pk2(h0, h1), pk2(h2, h3));
        reinterpret_cast<uint2*>(g_xl)[i] =
            make_uint2(pk2(v0 - h0, v1 - h1), pk2(v2 - h2, v3 - h3));
    }
}

// ---------------- launch 2: weight pack + degree count (fused) ------------
__global__ void k_pack_count(const float* __restrict__ W1,
                             const float* __restrict__ W2,
                             const float* __restrict__ W3,
                             const int* __restrict__ ei) {
    const int gid = blockIdx.x * blockDim.x + threadIdx.x;
    if (gid < NE) atomicAdd(&g_deg[ei[gid]], 1);

    const int T1 = DI * DI, T2 = 2 * DI * DI, T3 = 2 * DI * DI + DI * DO;
    for (int idx = gid; idx < T3; idx += gridDim.x * blockDim.x) {
        const float* W; __nv_bfloat16 *Wh, *Wl; int loc, N;
        if (idx < T1)      { W = W1; Wh = g_W1h; Wl = g_W1l; loc = idx;      N = DI; }
        else if (idx < T2) { W = W2; Wh = g_W2h; Wl = g_W2l; loc = idx - T1; N = DI; }
        else               { W = W3; Wh = g_W3h; Wl = g_W3l; loc = idx - T2; N = DO; }
        int k = loc / N, n = loc % N;
        float w = W[loc];
        __nv_bfloat16 hi = __float2bfloat16_rn(w);
        Wh[n * DI + k] = hi;
        Wl[n * DI + k] = __float2bfloat16_rn(w - __bfloat162float(hi));
    }
}

// ---------------- launch 3: block scan (+ dinv) ----------------
__global__ __launch_bounds__(1024) void k_scan_block() {
    __shared__ int s[1024];
    int tid = threadIdx.x;
    int i = blockIdx.x * 1024 + tid;
    int v = (i < NN) ? g_deg[i] : 0;
    if (i < NN) g_dinv[i] = rsqrtf((float)(v + 1));
    s[tid] = v;
    __syncthreads();
    #pragma unroll
    for (int off = 1; off < 1024; off <<= 1) {
        int t = (tid >= off) ? s[tid - off] : 0;
        __syncthreads();
        s[tid] += t;
        __syncthreads();
    }
    if (i < NN) g_rowptr[i] = s[tid] - v;
    if (tid == 1023) g_bsum[blockIdx.x] = s[1023];
}

// ---------------- launch 5: scan finalize (fused block-sum prefix) --------
__global__ void k_scan_addm() {
    __shared__ int pre[NSB];
    int tid = threadIdx.x;
    if (tid < NSB) pre[tid] = g_bsum[tid];
    __syncthreads();
    if (tid == 0) {
        int acc = 0;
        #pragma unroll
        for (int b = 0; b < NSB; b++) { int v = pre[b]; pre[b] = acc; acc += v; }
    }
    __syncthreads();
    int i = blockIdx.x * blockDim.x + tid;
    if (i < NN) {
        int v = g_rowptr[i] + pre[i >> 10];
        g_rowptr[i] = v;
        g_cursor[i] = v;
        if (i == 0) g_rowptr[NN] = NE;
    }
}

// ---------------- launch 6: CSR fill ----------------
__global__ void k_fill(const int* __restrict__ ei) {
    int e = blockIdx.x * blockDim.x + threadIdx.x;
    if (e < NE) {
        int r = ei[e], c = ei[NE + e];
        int pos = atomicAdd(&g_cursor[r], 1);
        g_col[pos]  = c;
        g_norm[pos] = g_dinv[r] * g_dinv[c];
    }
}

// ---------------- wide GEMM (layers 1-2): BM=128, BN=256, 512 threads ------
__global__ __launch_bounds__(512) void k_mma_wide(int layer) {
    const __nv_bfloat16* Wh = (layer == 0) ? g_W1h : g_W2h;
    const __nv_bfloat16* Wl = (layer == 0) ? g_W1l : g_W2l;

    extern __shared__ char smem[];
    const uint32_t sb = smem_u32(smem);
    const int tid = threadIdx.x;
    const int lane = tid & 31, wid = tid >> 5;     // 16 warps
    const int wm = (wid >> 2) * 32;                 // 0,32,64,96
    const int wn = (wid & 3) * 64;                  // 0,64,128,192
    const int rowBase = blockIdx.y * BM;

    float acc[2][8][4];
    #pragma unroll
    for (int a = 0; a < 2; a++)
        #pragma unroll
        for (int b = 0; b < 8; b++)
            #pragma unroll
            for (int c = 0; c < 4; c++) acc[a][b][c] = 0.f;

    auto fill = [&](int s, int k0) {
        #pragma unroll
        for (int i = 0; i < 6; i++) {
            int c = tid + i * 512;
            uint32_t dst;
            const __nv_bfloat16* src;
            uint32_t sz = 16;
            if (c < 1024) {                       // A images
                int img = c >> 9, r = (c >> 2) & 127, ch = c & 3;
                dst = sb + s * STAGE2 + img * 10240 + r * 80 + ch * 16;
                int gr = rowBase + r;
                const __nv_bfloat16* p = (img == 0) ? g_xh : g_xl;
                if (gr >= NN) { gr = 0; sz = 0; }
                src = p + (size_t)gr * DI + k0 + ch * 8;
            } else {                              // B images
                int d = c - 1024;
                int img = d >> 10, r = (d >> 2) & 255, ch = d & 3;
                dst = sb + s * STAGE2 + 20480 + img * 20480 + r * 80 + ch * 16;
                const __nv_bfloat16* p = (img == 0) ? Wh : Wl;
                src = p + (size_t)r * DI + k0 + ch * 8;
            }
            cpa16(dst, src, sz);
        }
    };

    fill(0, 0);
    CP_COMMIT();

    for (int step = 0; step < 8; step++) {
        const int s = step & 1;
        if (step < 7) { fill(s ^ 1, (step + 1) * 32); CP_COMMIT(); CP_WAIT1(); }
        else CP_WAIT0();
        __syncthreads();

        const uint32_t Ah = sb + s * STAGE2;
        const uint32_t Al = Ah + 10240;
        const uint32_t Bh = Ah + 20480;
        const uint32_t Bl = Ah + 40960;

        #pragma unroll
        for (int ks = 0; ks < 2; ks++) {
            uint32_t ah[2][4], al[2][4];
            const int arow = (lane & 7) + ((lane >> 3) & 1) * 8;
            const int akb  = ks * 32 + (lane >> 4) * 16;
            #pragma unroll
            for (int mt = 0; mt < 2; mt++) {
                uint32_t off = (uint32_t)(wm + mt * 16 + arow) * 80 + akb;
                LDSM4(ah[mt], Ah + off);
                LDSM4(al[mt], Al + off);
            }
            const int brow = (lane & 7) + ((lane >> 4) & 1) * 8;
            const int bkb  = ks * 32 + ((lane >> 3) & 1) * 16;
            #pragma unroll
            for (int p = 0; p < 4; p++) {
                uint32_t bh[4], bl[4];
                uint32_t off = (uint32_t)(wn + p * 16 + brow) * 80 + bkb;
                LDSM4(bh, Bh + off);
                LDSM4(bl, Bl + off);
                #pragma unroll
                for (int mt = 0; mt < 2; mt++) {
                    MMA(acc[mt][2 * p],     ah[mt], bh[0], bh[1]);
                    MMA(acc[mt][2 * p + 1], ah[mt], bh[2], bh[3]);
                    MMA(acc[mt][2 * p],     ah[mt], bl[0], bl[1]);
                    MMA(acc[mt][2 * p + 1], ah[mt], bl[2], bl[3]);
                    MMA(acc[mt][2 * p],     al[mt], bh[0], bh[1]);
                    MMA(acc[mt][2 * p + 1], al[mt], bh[2], bh[3]);
                }
            }
        }
        __syncthreads();
    }

    const int g = lane >> 2, t2 = (lane & 3) * 2;
    #pragma unroll
    for (int mt = 0; mt < 2; mt++) {
        int r0 = rowBase + wm + mt * 16 + g;
        #pragma unroll
        for (int nt = 0; nt < 8; nt++) {
            int col = wn + nt * 8 + t2;
            if (r0 < NN)
                *reinterpret_cast<float2*>(&g_h[(size_t)r0 * 256 + col]) =
                    make_float2(acc[mt][nt][0], acc[mt][nt][1]);
            if (r0 + 8 < NN)
                *reinterpret_cast<float2*>(&g_h[(size_t)(r0 + 8) * 256 + col]) =
                    make_float2(acc[mt][nt][2], acc[mt][nt][3]);
        }
    }
}

// ---------------- layer-3 GEMM: N=128, 256 threads ----------------
__global__ __launch_bounds__(256) void k_mma3() {
    const __nv_bfloat16* Wh = g_W3h;
    const __nv_bfloat16* Wl = g_W3l;
    const int N = 128;

    extern __shared__ char smem[];
    const uint32_t sb = smem_u32(smem);
    const int tid = threadIdx.x;
    const int lane = tid & 31, wid = tid >> 5;
    const int wm = (wid >> 1) * 32;
    const int wn = (wid & 1) * 64;
    const int rowBase = blockIdx.y * BM;

    float acc[2][8][4];
    #pragma unroll
    for (int a = 0; a < 2; a++)
        #pragma unroll
        for (int b = 0; b < 8; b++)
            #pragma unroll
            for (int c = 0; c < 4; c++) acc[a][b][c] = 0.f;

    auto fill = [&](int s, int k0) {
        #pragma unroll
        for (int i = 0; i < 8; i++) {
            int c = tid + i * 256;
            int img = c >> 9;
            int r   = (c >> 2) & 127;
            int ch  = c & 3;
            uint32_t dst = sb + s * STAGE + img * IMG + r * 80 + ch * 16;
            const __nv_bfloat16* src;
            uint32_t sz = 16;
            if (img < 2) {
                int gr = rowBase + r;
                const __nv_bfloat16* p = (img == 0) ? g_xh : g_xl;
                if (gr >= NN) { gr = 0; sz = 0; }
                src = p + (size_t)gr * DI + k0 + ch * 8;
            } else {
                const __nv_bfloat16* p = (img == 2) ? Wh : Wl;
                src = p + (size_t)r * DI + k0 + ch * 8;
            }
            cpa16(dst, src, sz);
        }
    };

    fill(0, 0);
    CP_COMMIT();

    for (int step = 0; step < 8; step++) {
        const int s = step & 1;
        if (step < 7) { fill(s ^ 1, (step + 1) * 32); CP_COMMIT(); CP_WAIT1(); }
        else CP_WAIT0();
        __syncthreads();

        const uint32_t Ah = sb + s * STAGE;
        const uint32_t Al = Ah + IMG;
        const uint32_t Bh = Ah + 2 * IMG;
        const uint32_t Bl = Ah + 3 * IMG;

        #pragma unroll
        for (int ks = 0; ks < 2; ks++) {
            uint32_t ah[2][4], al[2][4];
            const int arow = (lane & 7) + ((lane >> 3) & 1) * 8;
            const int akb  = ks * 32 + (lane >> 4) * 16;
            #pragma unroll
            for (int mt = 0; mt < 2; mt++) {
                uint32_t off = (uint32_t)(wm + mt * 16 + arow) * 80 + akb;
                LDSM4(ah[mt], Ah + off);
                LDSM4(al[mt], Al + off);
            }
            const int brow = (lane & 7) + ((lane >> 4) & 1) * 8;
            const int bkb  = ks * 32 + ((lane >> 3) & 1) * 16;
            #pragma unroll
            for (int p = 0; p < 4; p++) {
                uint32_t bh[4], bl[4];
                uint32_t off = (uint32_t)(wn + p * 16 + brow) * 80 + bkb;
                LDSM4(bh, Bh + off);
                LDSM4(bl, Bl + off);
                #pragma unroll
                for (int mt = 0; mt < 2; mt++) {
                    MMA(acc[mt][2 * p],     ah[mt], bh[0], bh[1]);
                    MMA(acc[mt][2 * p + 1], ah[mt], bh[2], bh[3]);
                    MMA(acc[mt][2 * p],     ah[mt], bl[0], bl[1]);
                    MMA(acc[mt][2 * p + 1], ah[mt], bl[2], bl[3]);
                    MMA(acc[mt][2 * p],     al[mt], bh[0], bh[1]);
                    MMA(acc[mt][2 * p + 1], al[mt], bh[2], bh[3]);
                }
            }
        }
        __syncthreads();
    }

    const int g = lane >> 2, t2 = (lane & 3) * 2;
    #pragma unroll
    for (int mt = 0; mt < 2; mt++) {
        int r0 = rowBase + wm + mt * 16 + g;
        #pragma unroll
        for (int nt = 0; nt < 8; nt++) {
            int col = wn + nt * 8 + t2;
            if (r0 < NN)
                *reinterpret_cast<float2*>(&g_h[(size_t)r0 * N + col]) =
                    make_float2(acc[mt][nt][0], acc[mt][nt][1]);
            if (r0 + 8 < NN)
                *reinterpret_cast<float2*>(&g_h[(size_t)(r0 + 8) * N + col]) =
                    make_float2(acc[mt][nt][2], acc[mt][nt][3]);
        }
    }
}

// ---------------- aggregation (round-5 proven form) ----------------
template <int D, bool HIDDEN>
__global__ void k_agg(const float* __restrict__ bias, float* __restrict__ outp) {
    const int i = blockIdx.x;
    const int t = threadIdx.x;
    const int beg = g_rowptr[i];
    const int end = g_rowptr[i + 1];
    const float di = g_dinv[i];
    const float4* __restrict__ h4 = reinterpret_cast<const float4*>(g_h);

    float4 acc = h4[(size_t)i * (D / 4) + t];
    const float s = di * di;
    acc.x *= s; acc.y *= s; acc.z *= s; acc.w *= s;

    for (int e = beg; e < end; e++) {
        int c = g_col[e];
        float w = g_norm[e];
        float4 v = h4[(size_t)c * (D / 4) + t];
        acc.x += w * v.x; acc.y += w * v.y; acc.z += w * v.z; acc.w += w * v.w;
    }

    float4 bv = reinterpret_cast<const float4*>(bias)[t];
    acc.x += bv.x; acc.y += bv.y; acc.z += bv.z; acc.w += bv.w;

    if (HIDDEN) {
        acc.x = fmaxf(acc.x, 0.f); acc.y = fmaxf(acc.y, 0.f);
        acc.z = fmaxf(acc.z, 0.f); acc.w = fmaxf(acc.w, 0.f);
        float h0 = __bfloat162float(__float2bfloat16_rn(acc.x));
        float h1 = __bfloat162float(__float2bfloat16_rn(acc.y));
        float h2 = __bfloat162float(__float2bfloat16_rn(acc.z));
        float h3 = __bfloat162float(__float2bfloat16_rn(acc.w));
        size_t o = (size_t)i * (D / 4) + t;
        reinterpret_cast<uint2*>(g_xh)[o] = make_uint2(pk2(h0, h1), pk2(h2, h3));
        reinterpret_cast<uint2*>(g_xl)[o] =
            make_uint2(pk2(acc.x - h0, acc.y - h1), pk2(acc.z - h2, acc.w - h3));
    } else {
        reinterpret_cast<float4*>(outp)[(size_t)i * (D / 4) + t] = acc;
    }
}

// ---------------- launch ----------------
extern "C" void kernel_launch(void* const* d_in, const int* in_sizes, int n_in,
                              void* d_out, int out_size) {
    const float* qe  = (const float*)d_in[0];
    const float* obj = (const float*)d_in[1];
    const int*   ei  = (const int*)d_in[2];
    const float* W1 = (const float*)d_in[3];
    const float* b1 = (const float*)d_in[4];
    const float* W2 = (const float*)d_in[5];
    const float* b2 = (const float*)d_in[6];
    const float* W3 = (const float*)d_in[7];
    const float* b3 = (const float*)d_in[8];
    float* out = (float*)d_out;

    const int SMEM_W = 2 * STAGE2;   // 122880
    const int SMEM_3 = 2 * STAGE;    // 81920
    static bool attr_done = false;
    if (!attr_done) {
        cudaFuncSetAttribute(k_mma_wide, cudaFuncAttributeMaxDynamicSharedMemorySize, SMEM_W);
        cudaFuncSetAttribute(k_mma3, cudaFuncAttributeMaxDynamicSharedMemorySize, SMEM_3);
        attr_done = true;
    }

    const int mb = (NN + BM - 1) / BM;    // 391

    // 1: x = qe * obj (bf16 hi/lo) + zero deg
    k_had<<<(NN * DI / 4 + 255) / 256, 256>>>((const float4*)qe, (const float4*)obj);
    // 2: weight pack + degree count (deg zeroed in launch 1)
    k_pack_count<<<(NE + 255) / 256, 256>>>(W1, W2, W3, ei);
    // 3: block scan + dinv
    k_scan_block<<<NSB, 1024>>>();
    // 4: layer-1 GEMM (independent of graph prep) — PROFILED SLOT
    k_mma_wide<<<dim3(1, mb), 512, SMEM_W>>>(0);
    // 5: scan finalize (fused block-sum prefix)
    k_scan_addm<<<(NN + 255) / 256, 256>>>();
    // 6: CSR fill
    k_fill<<<(NE + 255) / 256, 256>>>(ei);
    // 7: agg layer 1
    k_agg<DI, true><<<NN, DI / 4>>>(b1, nullptr);
    // 8-9: layer 2
    k_mma_wide<<<dim3(1, mb), 512, SMEM_W>>>(1);
    k_agg<DI, true><<<NN, DI / 4>>>(b2, nullptr);
    // 10-11: layer 3
    k_mma3<<<dim3(1, mb), 256, SMEM_3>>>();
    k_agg<DO, false><<<NN, DO / 4>>>(b3, out);
}

// round 14
// speedup vs baseline: 1.1878x; 1.0059x over previous
#include <cuda_runtime.h>
#include <cuda_bf16.h>
#include <cstdint>

// Problem constants
#define NN 50000
#define NE 800000
#define DI 256        // K for all layers
#define DO 128
#define BM 128
#define IMG 10240            // 128 rows * 80B padded
#define STAGE (4 * IMG)      // layer-3 kernel: Ah, Al, Bh, Bl
#define STAGE2 61440         // wide kernel: Ah,Al (2*10240) + Bh,Bl (2*20480)
#define NSB 49               // scan blocks: ceil(50000/1024)

// ---------------- device scratch ----------------
__device__ __nv_bfloat16 g_xh[NN * DI];   // activation hi (bf16)
__device__ __nv_bfloat16 g_xl[NN * DI];   // activation lo (bf16)
__device__ float g_h[NN * DI];            // post-GEMM fp32
__device__ int   g_deg[NN];
__device__ float g_dinv[NN];
__device__ int   g_rowptr[NN + 1];
__device__ int   g_cursor[NN];
__device__ int   g_col[NE];
__device__ float g_norm[NE];
__device__ int   g_bsum[64];

// transposed bf16 weight images: Wt[n][k], k contiguous (256 wide)
__device__ __nv_bfloat16 g_W1h[DI * DI], g_W1l[DI * DI];
__device__ __nv_bfloat16 g_W2h[DI * DI], g_W2l[DI * DI];
__device__ __nv_bfloat16 g_W3h[DO * DI], g_W3l[DO * DI];

// ---------------- small helpers ----------------
__device__ __forceinline__ uint32_t smem_u32(const void* p) {
    uint32_t a;
    asm("{ .reg .u64 t; cvta.to.shared.u64 t, %1; cvt.u32.u64 %0, t; }" : "=r"(a) : "l"(p));
    return a;
}
__device__ __forceinline__ uint32_t pk2(float a, float b) {
    __nv_bfloat162 t = __floats2bfloat162_rn(a, b);
    return *reinterpret_cast<uint32_t*>(&t);
}
__device__ __forceinline__ void cpa16(uint32_t dst, const void* src, uint32_t sz) {
    asm volatile("cp.async.cg.shared.global [%0], [%1], 16, %2;"
                 :: "r"(dst), "l"(src), "r"(sz));
}
#define CP_COMMIT() asm volatile("cp.async.commit_group;" ::: "memory")
#define CP_WAIT1()  asm volatile("cp.async.wait_group 1;" ::: "memory")
#define CP_WAIT0()  asm volatile("cp.async.wait_group 0;" ::: "memory")

#define LDSM4(r, a) \
    asm volatile("ldmatrix.sync.aligned.m8n8.x4.shared.b16 {%0,%1,%2,%3}, [%4];" \
                 : "=r"((r)[0]), "=r"((r)[1]), "=r"((r)[2]), "=r"((r)[3]) : "r"(a))

#define MMA(ac, a, bb0, bb1) \
    asm volatile("mma.sync.aligned.m16n8k16.row.col.f32.bf16.bf16.f32 " \
                 "{%0,%1,%2,%3},{%4,%5,%6,%7},{%8,%9},{%0,%1,%2,%3};" \
                 : "+f"((ac)[0]), "+f"((ac)[1]), "+f"((ac)[2]), "+f"((ac)[3]) \
                 : "r"((a)[0]), "r"((a)[1]), "r"((a)[2]), "r"((a)[3]), \
                   "r"(bb0), "r"(bb1))

// ---------------- launch 1: x = qe * obj -> bf16 hi/lo (+ zero g_deg) -----
__global__ void k_had(const float4* __restrict__ a, const float4* __restrict__ b) {
    int i = blockIdx.x * blockDim.x + threadIdx.x;
    if (i < NN) g_deg[i] = 0;
    const int n4 = NN * DI / 4;
    if (i < n4) {
        float4 va = a[i], vb = b[i];
        float v0 = va.x * vb.x, v1 = va.y * vb.y, v2 = va.z * vb.z, v3 = va.w * vb.w;
        float h0 = __bfloat162float(__float2bfloat16_rn(v0));
        float h1 = __bfloat162float(__float2bfloat16_rn(v1));
        float h2 = __bfloat162float(__float2bfloat16_rn(v2));
        float h3 = __bfloat162float(__float2bfloat16_rn(v3));
        reinterpret_cast<uint2*>(g_xh)[i] = make_uint2(pk2(h0, h1), pk2(h2, h3));
        reinterpret_cast<uint2*>(g_xl)[i] =
            make_uint2(pk2(v0 - h0, v1 - h1), pk2(v2 - h2, v3 - h3));
    }
}

// ---------------- launch 2: weight pack + degree count (fused) ------------
__global__ void k_pack_count(const float* __restrict__ W1,
                             const float* __restrict__ W2,
                             const float* __restrict__ W3,
                             const int* __restrict__ ei) {
    const int gid = blockIdx.x * blockDim.x + threadIdx.x;
    if (gid < NE) atomicAdd(&g_deg[ei[gid]], 1);

    const int T1 = DI * DI, T2 = 2 * DI * DI, T3 = 2 * DI * DI + DI * DO;
    for (int idx = gid; idx < T3; idx += gridDim.x * blockDim.x) {
        const float* W; __nv_bfloat16 *Wh, *Wl; int loc, N;
        if (idx < T1)      { W = W1; Wh = g_W1h; Wl = g_W1l; loc = idx;      N = DI; }
        else if (idx < T2) { W = W2; Wh = g_W2h; Wl = g_W2l; loc = idx - T1; N = DI; }
        else               { W = W3; Wh = g_W3h; Wl = g_W3l; loc = idx - T2; N = DO; }
        int k = loc / N, n = loc % N;
        float w = W[loc];
        __nv_bfloat16 hi = __float2bfloat16_rn(w);
        Wh[n * DI + k] = hi;
        Wl[n * DI + k] = __float2bfloat16_rn(w - __bfloat162float(hi));
    }
}

// ---------------- launch 3: block scan (+ dinv) ----------------
__global__ __launch_bounds__(1024) void k_scan_block() {
    __shared__ int s[1024];
    int tid = threadIdx.x;
    int i = blockIdx.x * 1024 + tid;
    int v = (i < NN) ? g_deg[i] : 0;
    if (i < NN) g_dinv[i] = rsqrtf((float)(v + 1));
    s[tid] = v;
    __syncthreads();
    #pragma unroll
    for (int off = 1; off < 1024; off <<= 1) {
        int t = (tid >= off) ? s[tid - off] : 0;
        __syncthreads();
        s[tid] += t;
        __syncthreads();
    }
    if (i < NN) g_rowptr[i] = s[tid] - v;
    if (tid == 1023) g_bsum[blockIdx.x] = s[1023];
}

// ---------------- launch 5: scan finalize (fused block-sum prefix) --------
__global__ void k_scan_addm() {
    __shared__ int pre[NSB];
    int tid = threadIdx.x;
    if (tid < NSB) pre[tid] = g_bsum[tid];
    __syncthreads();
    if (tid == 0) {
        int acc = 0;
        #pragma unroll
        for (int b = 0; b < NSB; b++) { int v = pre[b]; pre[b] = acc; acc += v; }
    }
    __syncthreads();
    int i = blockIdx.x * blockDim.x + tid;
    if (i < NN) {
        int v = g_rowptr[i] + pre[i >> 10];
        g_rowptr[i] = v;
        g_cursor[i] = v;
        if (i == 0) g_rowptr[NN] = NE;
    }
}

// ---------------- launch 6: CSR fill ----------------
__global__ void k_fill(const int* __restrict__ ei) {
    int e = blockIdx.x * blockDim.x + threadIdx.x;
    if (e < NE) {
        int r = ei[e], c = ei[NE + e];
        int pos = atomicAdd(&g_cursor[r], 1);
        g_col[pos]  = c;
        g_norm[pos] = g_dinv[r] * g_dinv[c];
    }
}

// ---------------- wide GEMM (layers 1-2): BM=128, BN=256, 512 threads ------
__global__ __launch_bounds__(512) void k_mma_wide(int layer) {
    const __nv_bfloat16* Wh = (layer == 0) ? g_W1h : g_W2h;
    const __nv_bfloat16* Wl = (layer == 0) ? g_W1l : g_W2l;

    extern __shared__ char smem[];
    const uint32_t sb = smem_u32(smem);
    const int tid = threadIdx.x;
    const int lane = tid & 31, wid = tid >> 5;     // 16 warps
    const int wm = (wid >> 2) * 32;                 // 0,32,64,96
    const int wn = (wid & 3) * 64;                  // 0,64,128,192
    const int rowBase = blockIdx.y * BM;

    float acc[2][8][4];
    #pragma unroll
    for (int a = 0; a < 2; a++)
        #pragma unroll
        for (int b = 0; b < 8; b++)
            #pragma unroll
            for (int c = 0; c < 4; c++) acc[a][b][c] = 0.f;

    auto fill = [&](int s, int k0) {
        #pragma unroll
        for (int i = 0; i < 6; i++) {
            int c = tid + i * 512;
            uint32_t dst;
            const __nv_bfloat16* src;
            uint32_t sz = 16;
            if (c < 1024) {                       // A images
                int img = c >> 9, r = (c >> 2) & 127, ch = c & 3;
                dst = sb + s * STAGE2 + img * 10240 + r * 80 + ch * 16;
                int gr = rowBase + r;
                const __nv_bfloat16* p = (img == 0) ? g_xh : g_xl;
                if (gr >= NN) { gr = 0; sz = 0; }
                src = p + (size_t)gr * DI + k0 + ch * 8;
            } else {                              // B images
                int d = c - 1024;
                int img = d >> 10, r = (d >> 2) & 255, ch = d & 3;
                dst = sb + s * STAGE2 + 20480 + img * 20480 + r * 80 + ch * 16;
                const __nv_bfloat16* p = (img == 0) ? Wh : Wl;
                src = p + (size_t)r * DI + k0 + ch * 8;
            }
            cpa16(dst, src, sz);
        }
    };

    fill(0, 0);
    CP_COMMIT();

    for (int step = 0; step < 8; step++) {
        const int s = step & 1;
        if (step < 7) { fill(s ^ 1, (step + 1) * 32); CP_COMMIT(); CP_WAIT1(); }
        else CP_WAIT0();
        __syncthreads();

        const uint32_t Ah = sb + s * STAGE2;
        const uint32_t Al = Ah + 10240;
        const uint32_t Bh = Ah + 20480;
        const uint32_t Bl = Ah + 40960;

        #pragma unroll
        for (int ks = 0; ks < 2; ks++) {
            uint32_t ah[2][4], al[2][4];
            const int arow = (lane & 7) + ((lane >> 3) & 1) * 8;
            const int akb  = ks * 32 + (lane >> 4) * 16;
            #pragma unroll
            for (int mt = 0; mt < 2; mt++) {
                uint32_t off = (uint32_t)(wm + mt * 16 + arow) * 80 + akb;
                LDSM4(ah[mt], Ah + off);
                LDSM4(al[mt], Al + off);
            }
            const int brow = (lane & 7) + ((lane >> 4) & 1) * 8;
            const int bkb  = ks * 32 + ((lane >> 3) & 1) * 16;
            #pragma unroll
            for (int p = 0; p < 4; p++) {
                uint32_t bh[4], bl[4];
                uint32_t off = (uint32_t)(wn + p * 16 + brow) * 80 + bkb;
                LDSM4(bh, Bh + off);
                LDSM4(bl, Bl + off);
                #pragma unroll
                for (int mt = 0; mt < 2; mt++) {
                    MMA(acc[mt][2 * p],     ah[mt], bh[0], bh[1]);
                    MMA(acc[mt][2 * p + 1], ah[mt], bh[2], bh[3]);
                    MMA(acc[mt][2 * p],     ah[mt], bl[0], bl[1]);
                    MMA(acc[mt][2 * p + 1], ah[mt], bl[2], bl[3]);
                    MMA(acc[mt][2 * p],     al[mt], bh[0], bh[1]);
                    MMA(acc[mt][2 * p + 1], al[mt], bh[2], bh[3]);
                }
            }
        }
        __syncthreads();
    }

    const int g = lane >> 2, t2 = (lane & 3) * 2;
    #pragma unroll
    for (int mt = 0; mt < 2; mt++) {
        int r0 = rowBase + wm + mt * 16 + g;
        #pragma unroll
        for (int nt = 0; nt < 8; nt++) {
            int col = wn + nt * 8 + t2;
            if (r0 < NN)
                *reinterpret_cast<float2*>(&g_h[(size_t)r0 * 256 + col]) =
                    make_float2(acc[mt][nt][0], acc[mt][nt][1]);
            if (r0 + 8 < NN)
                *reinterpret_cast<float2*>(&g_h[(size_t)(r0 + 8) * 256 + col]) =
                    make_float2(acc[mt][nt][2], acc[mt][nt][3]);
        }
    }
}

// ---------------- layer-3 GEMM: N=128, 256 threads ----------------
__global__ __launch_bounds__(256) void k_mma3() {
    const __nv_bfloat16* Wh = g_W3h;
    const __nv_bfloat16* Wl = g_W3l;
    const int N = 128;

    extern __shared__ char smem[];
    const uint32_t sb = smem_u32(smem);
    const int tid = threadIdx.x;
    const int lane = tid & 31, wid = tid >> 5;
    const int wm = (wid >> 1) * 32;
    const int wn = (wid & 1) * 64;
    const int rowBase = blockIdx.y * BM;

    float acc[2][8][4];
    #pragma unroll
    for (int a = 0; a < 2; a++)
        #pragma unroll
        for (int b = 0; b < 8; b++)
            #pragma unroll
            for (int c = 0; c < 4; c++) acc[a][b][c] = 0.f;

    auto fill = [&](int s, int k0) {
        #pragma unroll
        for (int i = 0; i < 8; i++) {
            int c = tid + i * 256;
            int img = c >> 9;
            int r   = (c >> 2) & 127;
            int ch  = c & 3;
            uint32_t dst = sb + s * STAGE + img * IMG + r * 80 + ch * 16;
            const __nv_bfloat16* src;
            uint32_t sz = 16;
            if (img < 2) {
                int gr = rowBase + r;
                const __nv_bfloat16* p = (img == 0) ? g_xh : g_xl;
                if (gr >= NN) { gr = 0; sz = 0; }
                src = p + (size_t)gr * DI + k0 + ch * 8;
            } else {
                const __nv_bfloat16* p = (img == 2) ? Wh : Wl;
                src = p + (size_t)r * DI + k0 + ch * 8;
            }
            cpa16(dst, src, sz);
        }
    };

    fill(0, 0);
    CP_COMMIT();

    for (int step = 0; step < 8; step++) {
        const int s = step & 1;
        if (step < 7) { fill(s ^ 1, (step + 1) * 32); CP_COMMIT(); CP_WAIT1(); }
        else CP_WAIT0();
        __syncthreads();

        const uint32_t Ah = sb + s * STAGE;
        const uint32_t Al = Ah + IMG;
        const uint32_t Bh = Ah + 2 * IMG;
        const uint32_t Bl = Ah + 3 * IMG;

        #pragma unroll
        for (int ks = 0; ks < 2; ks++) {
            uint32_t ah[2][4], al[2][4];
            const int arow = (lane & 7) + ((lane >> 3) & 1) * 8;
            const int akb  = ks * 32 + (lane >> 4) * 16;
            #pragma unroll
            for (int mt = 0; mt < 2; mt++) {
                uint32_t off = (uint32_t)(wm + mt * 16 + arow) * 80 + akb;
                LDSM4(ah[mt], Ah + off);
                LDSM4(al[mt], Al + off);
            }
            const int brow = (lane & 7) + ((lane >> 4) & 1) * 8;
            const int bkb  = ks * 32 + ((lane >> 3) & 1) * 16;
            #pragma unroll
            for (int p = 0; p < 4; p++) {
                uint32_t bh[4], bl[4];
                uint32_t off = (uint32_t)(wn + p * 16 + brow) * 80 + bkb;
                LDSM4(bh, Bh + off);
                LDSM4(bl, Bl + off);
                #pragma unroll
                for (int mt = 0; mt < 2; mt++) {
                    MMA(acc[mt][2 * p],     ah[mt], bh[0], bh[1]);
                    MMA(acc[mt][2 * p + 1], ah[mt], bh[2], bh[3]);
                    MMA(acc[mt][2 * p],     ah[mt], bl[0], bl[1]);
                    MMA(acc[mt][2 * p + 1], ah[mt], bl[2], bl[3]);
                    MMA(acc[mt][2 * p],     al[mt], bh[0], bh[1]);
                    MMA(acc[mt][2 * p + 1], al[mt], bh[2], bh[3]);
                }
            }
        }
        __syncthreads();
    }

    const int g = lane >> 2, t2 = (lane & 3) * 2;
    #pragma unroll
    for (int mt = 0; mt < 2; mt++) {
        int r0 = rowBase + wm + mt * 16 + g;
        #pragma unroll
        for (int nt = 0; nt < 8; nt++) {
            int col = wn + nt * 8 + t2;
            if (r0 < NN)
                *reinterpret_cast<float2*>(&g_h[(size_t)r0 * N + col]) =
                    make_float2(acc[mt][nt][0], acc[mt][nt][1]);
            if (r0 + 8 < NN)
                *reinterpret_cast<float2*>(&g_h[(size_t)(r0 + 8) * N + col]) =
                    make_float2(acc[mt][nt][2], acc[mt][nt][3]);
        }
    }
}

// ---------------- aggregation (round-5 proven form) ----------------
template <int D, bool HIDDEN>
__global__ void k_agg(const float* __restrict__ bias, float* __restrict__ outp) {
    const int i = blockIdx.x;
    const int t = threadIdx.x;
    const int beg = g_rowptr[i];
    const int end = g_rowptr[i + 1];
    const float di = g_dinv[i];
    const float4* __restrict__ h4 = reinterpret_cast<const float4*>(g_h);

    float4 acc = h4[(size_t)i * (D / 4) + t];
    const float s = di * di;
    acc.x *= s; acc.y *= s; acc.z *= s; acc.w *= s;

    for (int e = beg; e < end; e++) {
        int c = g_col[e];
        float w = g_norm[e];
        float4 v = h4[(size_t)c * (D / 4) + t];
        acc.x += w * v.x; acc.y += w * v.y; acc.z += w * v.z; acc.w += w * v.w;
    }

    float4 bv = reinterpret_cast<const float4*>(bias)[t];
    acc.x += bv.x; acc.y += bv.y; acc.z += bv.z; acc.w += bv.w;

    if (HIDDEN) {
        acc.x = fmaxf(acc.x, 0.f); acc.y = fmaxf(acc.y, 0.f);
        acc.z = fmaxf(acc.z, 0.f); acc.w = fmaxf(acc.w, 0.f);
        float h0 = __bfloat162float(__float2bfloat16_rn(acc.x));
        float h1 = __bfloat162float(__float2bfloat16_rn(acc.y));
        float h2 = __bfloat162float(__float2bfloat16_rn(acc.z));
        float h3 = __bfloat162float(__float2bfloat16_rn(acc.w));
        size_t o = (size_t)i * (D / 4) + t;
        reinterpret_cast<uint2*>(g_xh)[o] = make_uint2(pk2(h0, h1), pk2(h2, h3));
        reinterpret_cast<uint2*>(g_xl)[o] =
            make_uint2(pk2(acc.x - h0, acc.y - h1), pk2(acc.z - h2, acc.w - h3));
    } else {
        reinterpret_cast<float4*>(outp)[(size_t)i * (D / 4) + t] = acc;
    }
}

// ---------------- launch ----------------
extern "C" void kernel_launch(void* const* d_in, const int* in_sizes, int n_in,
                              void* d_out, int out_size) {
    const float* qe  = (const float*)d_in[0];
    const float* obj = (const float*)d_in[1];
    const int*   ei  = (const int*)d_in[2];
    const float* W1 = (const float*)d_in[3];
    const float* b1 = (const float*)d_in[4];
    const float* W2 = (const float*)d_in[5];
    const float* b2 = (const float*)d_in[6];
    const float* W3 = (const float*)d_in[7];
    const float* b3 = (const float*)d_in[8];
    float* out = (float*)d_out;

    const int SMEM_W = 2 * STAGE2;   // 122880
    const int SMEM_3 = 2 * STAGE;    // 81920
    static bool attr_done = false;
    if (!attr_done) {
        cudaFuncSetAttribute(k_mma_wide, cudaFuncAttributeMaxDynamicSharedMemorySize, SMEM_W);
        cudaFuncSetAttribute(k_mma3, cudaFuncAttributeMaxDynamicSharedMemorySize, SMEM_3);
        attr_done = true;
    }

    const int mb = (NN + BM - 1) / BM;    // 391

    // 1: x = qe * obj (bf16 hi/lo) + zero deg
    k_had<<<(NN * DI / 4 + 255) / 256, 256>>>((const float4*)qe, (const float4*)obj);
    // 2: weight pack + degree count (deg zeroed in launch 1)
    k_pack_count<<<(NE + 255) / 256, 256>>>(W1, W2, W3, ei);
    // 3: block scan + dinv
    k_scan_block<<<NSB, 1024>>>();
    // 4: layer-1 GEMM (independent of graph prep) — PROFILED SLOT
    k_mma_wide<<<dim3(1, mb), 512, SMEM_W>>>(0);
    // 5: scan finalize (fused block-sum prefix)
    k_scan_addm<<<(NN + 255) / 256, 256>>>();
    // 6: CSR fill
    k_fill<<<(NE + 255) / 256, 256>>>(ei);
    // 7: agg layer 1
    k_agg<DI, true><<<NN, DI / 4>>>(b1, nullptr);
    // 8-9: layer 2
    k_mma_wide<<<dim3(1, mb), 512, SMEM_W>>>(1);
    k_agg<DI, true><<<NN, DI / 4>>>(b2, nullptr);
    // 10-11: layer 3
    k_mma3<<<dim3(1, mb), 256, SMEM_3>>>();
    k_agg<DO, false><<<NN, DO / 4>>>(b3, out);
}